// round 8
// baseline (speedup 1.0000x reference)
#include <cuda_runtime.h>
#include <math.h>

#define B_     64
#define NSIDE  40
#define NPTS   1600
#define S_     512
#define C1_    20
#define W_     128
#define SCN    10240                 // S_*C1_
#define KSPLIT 8                     // k2 n-dim split (200 each)
#define GSPLIT 16                    // kG s-splits (32 s each)
#define ZSPLIT 86                    // kZ kc-splits (30 each)
#define KCH    25                    // k2 k-chunk (8 chunks per 200)

typedef unsigned long long u64;

// ---------------- scratch (device globals; no runtime allocation) ----------------
__device__ __align__(16) float g_filt1[S_ * C1_ * NPTS];   // [sc][n]
__device__ __align__(16) float g_z1  [SCN * B_];           // atomic accum [sc][b]
__device__ __align__(16) float g_h2  [S_ * W_];            // [s][128]
__device__ __align__(16) float g_G   [129 * 1280];         // atomic accum [k][c*64+b]
__device__ __align__(16) float g_z2  [B_ * W_];            // atomic accum [b][w]

// ---------------- f32x2 helpers (Blackwell packed fp32 FMA) -----------------------
__device__ __forceinline__ u64 pk2(float lo, float hi) {
    u64 r; asm("mov.b64 %0, {%1, %2};" : "=l"(r) : "f"(lo), "f"(hi)); return r;
}
__device__ __forceinline__ void upk2(u64 v, float& lo, float& hi) {
    asm("mov.b64 {%0, %1}, %2;" : "=f"(lo), "=f"(hi) : "l"(v));
}
__device__ __forceinline__ void fma2p(u64& d, u64 a, u64 b) {
    asm("fma.rn.f32x2 %0, %1, %2, %0;" : "+l"(d) : "l"(a), "l"(b));
}

__device__ __forceinline__ float silu_f(float x) { return x / (1.0f + __expf(-x)); }
__device__ __forceinline__ float silu_t(float x) {
    float t; asm("tanh.approx.f32 %0, %1;" : "=f"(t) : "f"(0.5f * x));
    return 0.5f * x * (1.0f + t);
}

// ---------------- K0: zero the atomic accumulators (per replay) -------------------
__global__ __launch_bounds__(256) void kzero()
{
    int i = blockIdx.x * 256 + threadIdx.x;
    float4 z = make_float4(0.f, 0.f, 0.f, 0.f);
    ((float4*)g_z1)[i] = z;                        // 163840 float4
    if (i < 129 * 1280 / 4) ((float4*)g_G)[i] = z;
    if (i < B_ * W_ / 4)    ((float4*)g_z2)[i] = z;
}

// ---------------- K1: filt1[sc][n] = MLP(embed(projective coords)) ----------------
#define BP 264   // buf row stride [feat][point]

__device__ __forceinline__ void k1_layer(const float* in, float* out,
                                         const float* w, const float* bias,
                                         int og, int pl)
{
    int ob = og * 10;
    u64 acc[4][5];
#pragma unroll
    for (int ip = 0; ip < 4; ip++)
#pragma unroll
        for (int j = 0; j < 5; j++) acc[ip][j] = pk2(bias[ob + 2*j], bias[ob + 2*j + 1]);
#pragma unroll 4
    for (int i = 0; i < 20; i++) {
        u64 wv[5];
#pragma unroll
        for (int j = 0; j < 5; j++)
            wv[j] = *(const u64*)&w[i * 20 + ob + 2 * j];
#pragma unroll
        for (int ip = 0; ip < 4; ip++) {
            float e = in[i * BP + pl + 64 * ip];
            u64 ed = pk2(e, e);
#pragma unroll
            for (int j = 0; j < 5; j++) fma2p(acc[ip][j], ed, wv[j]);
        }
    }
#pragma unroll
    for (int ip = 0; ip < 4; ip++)
#pragma unroll
        for (int j = 0; j < 5; j++) {
            float a0, a1; upk2(acc[ip][j], a0, a1);
            out[(ob + 2*j)     * BP + pl + 64 * ip] = silu_t(a0);
            out[(ob + 2*j + 1) * BP + pl + 64 * ip] = silu_t(a1);
        }
}

__global__ __launch_bounds__(128) void k1_filt1(
    const float* __restrict__ v_last,
    const float* __restrict__ fw1, const float* __restrict__ fb1,
    const float* __restrict__ fw2, const float* __restrict__ fb2,
    const float* __restrict__ fw3, const float* __restrict__ fb3)
{
    __shared__ __align__(16) float sw1[400], sw2[400], sw3[400];
    __shared__ float sb1[20], sb2[20], sb3[20];
    __shared__ __align__(16) float bufA[20 * BP], bufB[20 * BP];

    int s   = blockIdx.y;
    int n0  = blockIdx.x * 256;
    int tid = threadIdx.x;

    for (int i = tid; i < 400; i += 128) { sw1[i] = fw1[i]; sw2[i] = fw2[i]; sw3[i] = fw3[i]; }
    if (tid < 20) { sb1[tid] = fb1[tid]; sb2[tid] = fb2[tid]; sb3[tid] = fb3[tid]; }

    float v[8];
#pragma unroll
    for (int i = 0; i < 8; i++) v[i] = 0.1f * __ldg(&v_last[s * 8 + i]);

#pragma unroll
    for (int q = 0; q < 2; q++) {
        int p = tid + q * 128;
        int n = n0 + p;
        int ic = n / NSIDE, jc = n - ic * NSIDE;
        float x = -1.0f + (2.0f / 39.0f) * (float)ic;
        float y = -1.0f + (2.0f / 39.0f) * (float)jc;
        float y0 = (1.0f + v[0]) * x + v[1] * y + v[2];
        float y1 = v[3] * x + (1.0f + v[4]) * y + v[5];
        float y2 = v[6] * x + v[7] * y + 1.0f;
        float inv = __frcp_rn(y2);
        float t0 = y0 * inv, t1 = y1 * inv;

        float sa, ca; __sincosf(t0, &sa, &ca);
        bufA[0 * BP + p] = sa; bufA[5 * BP + p] = ca;
#pragma unroll
        for (int k = 1; k < 5; k++) {
            float s2 = 2.0f * sa * ca;
            float c2 = 2.0f * ca * ca - 1.0f;
            bufA[k * BP + p] = s2; bufA[(5 + k) * BP + p] = c2;
            sa = s2; ca = c2;
        }
        __sincosf(t1, &sa, &ca);
        bufA[10 * BP + p] = sa; bufA[15 * BP + p] = ca;
#pragma unroll
        for (int k = 1; k < 5; k++) {
            float s2 = 2.0f * sa * ca;
            float c2 = 2.0f * ca * ca - 1.0f;
            bufA[(10 + k) * BP + p] = s2; bufA[(15 + k) * BP + p] = c2;
            sa = s2; ca = c2;
        }
    }
    __syncthreads();

    int og = tid >> 6;
    int pl = tid & 63;

    k1_layer(bufA, bufB, sw1, sb1, og, pl);
    __syncthreads();
    k1_layer(bufB, bufA, sw2, sb2, og, pl);
    __syncthreads();

    {
        int ob = og * 10;
        u64 acc[4][5];
#pragma unroll
        for (int ip = 0; ip < 4; ip++)
#pragma unroll
            for (int j = 0; j < 5; j++) acc[ip][j] = pk2(sb3[ob + 2*j], sb3[ob + 2*j + 1]);
#pragma unroll 4
        for (int i = 0; i < 20; i++) {
            u64 wv[5];
#pragma unroll
            for (int j = 0; j < 5; j++) wv[j] = *(const u64*)&sw3[i * 20 + ob + 2 * j];
#pragma unroll
            for (int ip = 0; ip < 4; ip++) {
                float e = bufA[i * BP + pl + 64 * ip];
                u64 ed = pk2(e, e);
#pragma unroll
                for (int j = 0; j < 5; j++) fma2p(acc[ip][j], ed, wv[j]);
            }
        }
#pragma unroll
        for (int ip = 0; ip < 4; ip++) {
            int n = n0 + pl + 64 * ip;
            if (n < NPTS) {
#pragma unroll
                for (int j = 0; j < 5; j++) {
                    float a0, a1; upk2(acc[ip][j], a0, a1);
                    g_filt1[(s * C1_ + ob + 2*j)     * NPTS + n] = a0;
                    g_filt1[(s * C1_ + ob + 2*j + 1) * NPTS + n] = a1;
                }
            }
        }
    }
}

// ---------------- K2: g_z1[sc][b] += filt1 . data over 200-wide n-range -----------
// Block tile 256sc x 32b, 256 threads, per-thread 4 sc-pairs x 4 b.
// Per k per warp: 2 LDS.128 (filter pairs, sr-grouped conflict-free) +
// 2 LDS.128 (dup'd data b-pairs) = 4 wf vs 16 FFMA2 (8 FMA-cyc) -> LDS:FMA = 0.5.
// smem 32.8 KB, ~60 regs -> 4 blocks/SM; grid 640.
__global__ __launch_bounds__(256, 4) void k2_z1(const float* __restrict__ data)
{
    __shared__ __align__(16) float ft[KCH * 260];   // [k][sc], stride 260 (16B-aligned rows)
    __shared__ __align__(16) u64  dtd[KCH * 34];    // [k][bl] dup pairs, stride 34 (even)

    int sc0   = (blockIdx.x >> 1) * 256;
    int b0    = (blockIdx.x & 1) * 32;
    int split = blockIdx.y;
    int tid   = threadIdx.x;
    int tc    = tid & 7;      // b-pair group: b = b0 + 2*tc + (0|1) + 16*jq
    int sr    = tid >> 3;     // sc octet: sc = sc0 + 8*sr + 2*p + (0|1)

    u64 acc[4][4];            // [sc-pair p][b j]
#pragma unroll
    for (int p = 0; p < 4; p++)
#pragma unroll
        for (int j = 0; j < 4; j++) acc[p][j] = 0ull;

    for (int ch = 0; ch < 8; ch++) {
        int base = split * 200 + ch * KCH;
        __syncthreads();
        for (int i = tid; i < 256 * KCH; i += 256) {      // coalesced 25-float runs
            int r = i / KCH, k = i - r * KCH;
            ft[k * 260 + r] = g_filt1[(sc0 + r) * NPTS + base + k];
        }
        for (int i = tid; i < 32 * KCH; i += 256) {
            int bl = i / KCH, k = i - bl * KCH;
            float d = data[(b0 + bl) * NPTS + base + k];
            dtd[k * 34 + bl] = pk2(d, d);
        }
        __syncthreads();

#pragma unroll 5
        for (int k = 0; k < KCH; k++) {
            ulonglong2 fA = *(const ulonglong2*)&ft[k * 260 + 8 * sr];
            ulonglong2 fB = *(const ulonglong2*)&ft[k * 260 + 8 * sr + 4];
            ulonglong2 dA = *(const ulonglong2*)&dtd[k * 34 + 2 * tc];
            ulonglong2 dB = *(const ulonglong2*)&dtd[k * 34 + 2 * tc + 16];
            u64 fd[4] = { fA.x, fA.y, fB.x, fB.y };
            u64 dd[4] = { dA.x, dA.y, dB.x, dB.y };
#pragma unroll
            for (int p = 0; p < 4; p++)
#pragma unroll
                for (int j = 0; j < 4; j++)
                    fma2p(acc[p][j], fd[p], dd[j]);
        }
    }

#pragma unroll
    for (int p = 0; p < 4; p++) {
        int sc = sc0 + 8 * sr + 2 * p;
#pragma unroll
        for (int j = 0; j < 4; j++) {
            int b = b0 + 2 * tc + (j & 1) + 16 * (j >> 1);
            float a0, a1; upk2(acc[p][j], a0, a1);
            atomicAdd(&g_z1[sc * B_ + b],       a0);
            atomicAdd(&g_z1[(sc + 1) * B_ + b], a1);
        }
    }
}

// ---------------- K3a: h2[s,:] = silu(embed(v0[s]) @ s_w1 + s_b1) -----------------
__global__ __launch_bounds__(128) void k3a_h2(const float* __restrict__ v0,
                                              const float* __restrict__ s_w1,
                                              const float* __restrict__ s_b1)
{
    __shared__ float e[80];
    int s = blockIdx.x, tid = threadIdx.x;
    if (tid < 80) {
        int d = tid / 10, kk = tid % 10;
        float v = v0[s * 8 + d];
        float f = (float)(1 << (kk % 5));
        e[tid] = (kk < 5) ? __sinf(v * f) : __cosf(v * f);
    }
    __syncthreads();
    float a = s_b1[tid];
#pragma unroll 8
    for (int k = 0; k < 80; k++) a += e[k] * s_w1[k * W_ + tid];
    g_h2[s * W_ + tid] = silu_f(a);
}

// ---------------- KG: g_G[k,cb] += sum over 32 s of h2e[s,k] * silu(z1/N)[s,cb] ---
__global__ __launch_bounds__(256) void kG_contract()
{
    __shared__ float h2s[32 * 129];   // [sl][k], k==128 -> 1 (bias column)
    __shared__ float z1s[32 * 81];    // [sl][cbl]
    int cb0 = blockIdx.x * 80;
    int s0  = blockIdx.y * 32;
    int tid = threadIdx.x;

    for (int i = tid; i < 32 * 32; i += 256) {
        int r = i >> 5, k4 = i & 31;
        float4 v = *(const float4*)&g_h2[(s0 + r) * W_ + 4 * k4];
        h2s[r * 129 + 4 * k4 + 0] = v.x; h2s[r * 129 + 4 * k4 + 1] = v.y;
        h2s[r * 129 + 4 * k4 + 2] = v.z; h2s[r * 129 + 4 * k4 + 3] = v.w;
    }
    if (tid < 32) h2s[tid * 129 + 128] = 1.0f;

    for (int i = tid; i < 32 * 20; i += 256) {
        int r = i / 20, c4 = i - r * 20;
        float4 a = *(const float4*)&g_z1[(s0 + r) * 1280 + cb0 + 4 * c4];
        float* zr = &z1s[r * 81 + 4 * c4];
        zr[0] = silu_f(a.x * (1.0f / (float)NPTS));
        zr[1] = silu_f(a.y * (1.0f / (float)NPTS));
        zr[2] = silu_f(a.z * (1.0f / (float)NPTS));
        zr[3] = silu_f(a.w * (1.0f / (float)NPTS));
    }
    __syncthreads();

    int kq  = tid & 15;   // k = kq + 16*j (j<8), plus k=128 when kq==0
    int cbq = tid >> 4;   // cb = cbq + 16*i (i<5)

    float acc[9][5];
#pragma unroll
    for (int j = 0; j < 9; j++)
#pragma unroll
        for (int i = 0; i < 5; i++) acc[j][i] = 0.0f;

    for (int sl = 0; sl < 32; sl++) {
        float h[9];
#pragma unroll
        for (int j = 0; j < 8; j++) h[j] = h2s[sl * 129 + kq + 16 * j];
        h[8] = h2s[sl * 129 + 128];
        float z[5];
#pragma unroll
        for (int i = 0; i < 5; i++) z[i] = z1s[sl * 81 + cbq + 16 * i];
#pragma unroll
        for (int j = 0; j < 9; j++)
#pragma unroll
            for (int i = 0; i < 5; i++) acc[j][i] += h[j] * z[i];
    }

#pragma unroll
    for (int j = 0; j < 9; j++) {
        int k = kq + 16 * j;
        if (j < 8 || kq == 0) {
#pragma unroll
            for (int i = 0; i < 5; i++)
                atomicAdd(&g_G[k * 1280 + cb0 + cbq + 16 * i], acc[j][i]);
        }
    }
}

// ---------------- KZ: g_z2[b][w] += sum over 30 kc of G[k,cb] * W2ext -------------
__global__ __launch_bounds__(256) void kZ_out(const float* __restrict__ s_w2,
                                              const float* __restrict__ s_b2)
{
    __shared__ float Gt[30 * 64];    // [kcl][b]
    __shared__ float Wt[30 * 128];   // [kcl][w]
    int kc0 = blockIdx.x * 30;
    int tid = threadIdx.x;

    for (int i = tid; i < 30 * 32; i += 256) {
        int kcl = i >> 5, w4 = i & 31;
        int kc = kc0 + kcl, k = kc / 20, c = kc - k * 20;
        float4 v = (k < 128) ? *(const float4*)&s_w2[k * 2560 + c * 128 + 4 * w4]
                             : *(const float4*)&s_b2[c * 128 + 4 * w4];
        *(float4*)&Wt[kcl * 128 + 4 * w4] = v;
    }
    for (int i = tid; i < 30 * 16; i += 256) {
        int kcl = i >> 4, b4 = i & 15;
        int kc = kc0 + kcl, k = kc / 20, c = kc - k * 20;
        float4 a = *(const float4*)&g_G[k * 1280 + c * 64 + 4 * b4];
        *(float4*)&Gt[kcl * 64 + 4 * b4] = a;
    }
    __syncthreads();

    int wq = tid & 15;   // w = wq + 16*m
    int bq = tid >> 4;   // b = bq + 16*i
    float acc[4][8];
#pragma unroll
    for (int i = 0; i < 4; i++)
#pragma unroll
        for (int m = 0; m < 8; m++) acc[i][m] = 0.0f;

    for (int kcl = 0; kcl < 30; kcl++) {
        float g[4];
#pragma unroll
        for (int i = 0; i < 4; i++) g[i] = Gt[kcl * 64 + bq + 16 * i];
#pragma unroll
        for (int m = 0; m < 8; m++) {
            float w = Wt[kcl * 128 + wq + 16 * m];
#pragma unroll
            for (int i = 0; i < 4; i++) acc[i][m] += g[i] * w;
        }
    }
#pragma unroll
    for (int i = 0; i < 4; i++)
#pragma unroll
        for (int m = 0; m < 8; m++)
            atomicAdd(&g_z2[(bq + 16 * i) * W_ + wq + 16 * m], acc[i][m]);
}

// ---------------- K5: residual MLP + pool -----------------------------------------
__global__ __launch_bounds__(128) void k5_head(const float* __restrict__ fc1_w,
                                               const float* __restrict__ fc1_b,
                                               const float* __restrict__ fc2_w,
                                               const float* __restrict__ fc2_b,
                                               const float* __restrict__ pool_w,
                                               const float* __restrict__ pool_b,
                                               float* __restrict__ out)
{
    __shared__ float zs[128], r1[128], r2[128];
    int b = blockIdx.x, w = threadIdx.x;

    float a = g_z2[b * W_ + w] * (1.0f / (float)S_);
    zs[w] = a;
    __syncthreads();

    float u = fc1_b[w];
#pragma unroll 8
    for (int k = 0; k < 128; k++) u += zs[k] * fc1_w[k * W_ + w];
    r1[w] = silu_f(u) + zs[w];
    __syncthreads();

    u = fc2_b[w];
#pragma unroll 8
    for (int k = 0; k < 128; k++) u += r1[k] * fc2_w[k * W_ + w];
    r2[w] = silu_f(u) + r1[w];
    __syncthreads();

    if (w < 10) {
        float o = pool_b[w];
        for (int k = 0; k < 128; k++) o += r2[k] * pool_w[k * 10 + w];
        out[b * 10 + w] = o;
    }
}

// ---------------- host launcher ---------------------------------------------------
extern "C" void kernel_launch(void* const* d_in, const int* in_sizes, int n_in,
                              void* d_out, int out_size)
{
    const float* data   = (const float*)d_in[0];
    const float* v0     = (const float*)d_in[1];
    const float* v_last = (const float*)d_in[2];
    const float* fl_w1  = (const float*)d_in[3];
    const float* fl_b1  = (const float*)d_in[4];
    const float* fl_w2  = (const float*)d_in[5];
    const float* fl_b2  = (const float*)d_in[6];
    const float* fl_w3  = (const float*)d_in[7];
    const float* fl_b3  = (const float*)d_in[8];
    const float* s_w1   = (const float*)d_in[9];
    const float* s_b1   = (const float*)d_in[10];
    const float* s_w2   = (const float*)d_in[11];
    const float* s_b2   = (const float*)d_in[12];
    const float* fc1_w  = (const float*)d_in[13];
    const float* fc1_b  = (const float*)d_in[14];
    const float* fc2_w  = (const float*)d_in[15];
    const float* fc2_b  = (const float*)d_in[16];
    const float* pool_w = (const float*)d_in[17];
    const float* pool_b = (const float*)d_in[18];

    kzero<<<640, 256>>>();
    k3a_h2<<<S_, 128>>>(v0, s_w1, s_b1);
    k1_filt1<<<dim3(7, S_), 128>>>(v_last, fl_w1, fl_b1, fl_w2, fl_b2, fl_w3, fl_b3);
    k2_z1<<<dim3(80, KSPLIT), 256>>>(data);
    kG_contract<<<dim3(16, GSPLIT), 256>>>();
    kZ_out<<<ZSPLIT, 256>>>(s_w2, s_b2);
    k5_head<<<B_, 128>>>(fc1_w, fc1_b, fc2_w, fc2_b, pool_w, pool_b, (float*)d_out);
}

// round 9
// speedup vs baseline: 1.2390x; 1.2390x over previous
#include <cuda_runtime.h>
#include <math.h>

#define B_     64
#define NSIDE  40
#define NPTS   1600
#define S_     512
#define C1_    20
#define W_     128
#define SCN    10240                 // S_*C1_
#define KSPLIT 5                     // k2 n-dim split (320 each)
#define GSPLIT 16                    // kG s-splits (32 s each)
#define ZSPLIT 86                    // kZ kc-splits (30 each)
#define KCH2   20                    // k2 k-chunk
#define NCH2   16                    // chunks per 320-split

typedef unsigned long long u64;

// ---------------- scratch (device globals; no runtime allocation) ----------------
__device__ __align__(16) float g_filt1[S_ * C1_ * NPTS];   // [sc][n]
__device__ __align__(16) float g_z1  [SCN * B_];           // atomic accum [sc][b]
__device__ __align__(16) float g_h2  [S_ * W_];            // [s][128]
__device__ __align__(16) float g_G   [129 * 1280];         // atomic accum [k][c*64+b]
__device__ __align__(16) float g_z2  [B_ * W_];            // atomic accum [b][w]

// ---------------- f32x2 helpers (Blackwell packed fp32 FMA) -----------------------
__device__ __forceinline__ u64 pk2(float lo, float hi) {
    u64 r; asm("mov.b64 %0, {%1, %2};" : "=l"(r) : "f"(lo), "f"(hi)); return r;
}
__device__ __forceinline__ void upk2(u64 v, float& lo, float& hi) {
    asm("mov.b64 {%0, %1}, %2;" : "=f"(lo), "=f"(hi) : "l"(v));
}
__device__ __forceinline__ void fma2p(u64& d, u64 a, u64 b) {
    asm("fma.rn.f32x2 %0, %1, %2, %0;" : "+l"(d) : "l"(a), "l"(b));
}

__device__ __forceinline__ float silu_f(float x) { return x / (1.0f + __expf(-x)); }
__device__ __forceinline__ float silu_t(float x) {
    float t; asm("tanh.approx.f32 %0, %1;" : "=f"(t) : "f"(0.5f * x));
    return 0.5f * x * (1.0f + t);
}

// ---------------- K0: zero the atomic accumulators (per replay) -------------------
__global__ __launch_bounds__(256) void kzero()
{
    int i = blockIdx.x * 256 + threadIdx.x;
    float4 z = make_float4(0.f, 0.f, 0.f, 0.f);
    ((float4*)g_z1)[i] = z;                        // 163840 float4
    if (i < 129 * 1280 / 4) ((float4*)g_G)[i] = z;
    if (i < B_ * W_ / 4)    ((float4*)g_z2)[i] = z;
}

// ---------------- K1: filt1[sc][n] = MLP(embed(projective coords)) ----------------
#define BP 264   // buf row stride [feat][point]

__device__ __forceinline__ void k1_layer(const float* in, float* out,
                                         const float* w, const float* bias,
                                         int og, int pl)
{
    int ob = og * 10;
    u64 acc[4][5];
#pragma unroll
    for (int ip = 0; ip < 4; ip++)
#pragma unroll
        for (int j = 0; j < 5; j++) acc[ip][j] = pk2(bias[ob + 2*j], bias[ob + 2*j + 1]);
#pragma unroll 4
    for (int i = 0; i < 20; i++) {
        u64 wv[5];
#pragma unroll
        for (int j = 0; j < 5; j++)
            wv[j] = *(const u64*)&w[i * 20 + ob + 2 * j];
#pragma unroll
        for (int ip = 0; ip < 4; ip++) {
            float e = in[i * BP + pl + 64 * ip];
            u64 ed = pk2(e, e);
#pragma unroll
            for (int j = 0; j < 5; j++) fma2p(acc[ip][j], ed, wv[j]);
        }
    }
#pragma unroll
    for (int ip = 0; ip < 4; ip++)
#pragma unroll
        for (int j = 0; j < 5; j++) {
            float a0, a1; upk2(acc[ip][j], a0, a1);
            out[(ob + 2*j)     * BP + pl + 64 * ip] = silu_t(a0);
            out[(ob + 2*j + 1) * BP + pl + 64 * ip] = silu_t(a1);
        }
}

__global__ __launch_bounds__(128) void k1_filt1(
    const float* __restrict__ v_last,
    const float* __restrict__ fw1, const float* __restrict__ fb1,
    const float* __restrict__ fw2, const float* __restrict__ fb2,
    const float* __restrict__ fw3, const float* __restrict__ fb3)
{
    __shared__ __align__(16) float sw1[400], sw2[400], sw3[400];
    __shared__ float sb1[20], sb2[20], sb3[20];
    __shared__ __align__(16) float bufA[20 * BP], bufB[20 * BP];

    int s   = blockIdx.y;
    int n0  = blockIdx.x * 256;
    int tid = threadIdx.x;

    for (int i = tid; i < 400; i += 128) { sw1[i] = fw1[i]; sw2[i] = fw2[i]; sw3[i] = fw3[i]; }
    if (tid < 20) { sb1[tid] = fb1[tid]; sb2[tid] = fb2[tid]; sb3[tid] = fb3[tid]; }

    float v[8];
#pragma unroll
    for (int i = 0; i < 8; i++) v[i] = 0.1f * __ldg(&v_last[s * 8 + i]);

#pragma unroll
    for (int q = 0; q < 2; q++) {
        int p = tid + q * 128;
        int n = n0 + p;
        int ic = n / NSIDE, jc = n - ic * NSIDE;
        float x = -1.0f + (2.0f / 39.0f) * (float)ic;
        float y = -1.0f + (2.0f / 39.0f) * (float)jc;
        float y0 = (1.0f + v[0]) * x + v[1] * y + v[2];
        float y1 = v[3] * x + (1.0f + v[4]) * y + v[5];
        float y2 = v[6] * x + v[7] * y + 1.0f;
        float inv = __frcp_rn(y2);
        float t0 = y0 * inv, t1 = y1 * inv;

        float sa, ca; __sincosf(t0, &sa, &ca);
        bufA[0 * BP + p] = sa; bufA[5 * BP + p] = ca;
#pragma unroll
        for (int k = 1; k < 5; k++) {
            float s2 = 2.0f * sa * ca;
            float c2 = 2.0f * ca * ca - 1.0f;
            bufA[k * BP + p] = s2; bufA[(5 + k) * BP + p] = c2;
            sa = s2; ca = c2;
        }
        __sincosf(t1, &sa, &ca);
        bufA[10 * BP + p] = sa; bufA[15 * BP + p] = ca;
#pragma unroll
        for (int k = 1; k < 5; k++) {
            float s2 = 2.0f * sa * ca;
            float c2 = 2.0f * ca * ca - 1.0f;
            bufA[(10 + k) * BP + p] = s2; bufA[(15 + k) * BP + p] = c2;
            sa = s2; ca = c2;
        }
    }
    __syncthreads();

    int og = tid >> 6;
    int pl = tid & 63;

    k1_layer(bufA, bufB, sw1, sb1, og, pl);
    __syncthreads();
    k1_layer(bufB, bufA, sw2, sb2, og, pl);
    __syncthreads();

    {
        int ob = og * 10;
        u64 acc[4][5];
#pragma unroll
        for (int ip = 0; ip < 4; ip++)
#pragma unroll
            for (int j = 0; j < 5; j++) acc[ip][j] = pk2(sb3[ob + 2*j], sb3[ob + 2*j + 1]);
#pragma unroll 4
        for (int i = 0; i < 20; i++) {
            u64 wv[5];
#pragma unroll
            for (int j = 0; j < 5; j++) wv[j] = *(const u64*)&sw3[i * 20 + ob + 2 * j];
#pragma unroll
            for (int ip = 0; ip < 4; ip++) {
                float e = bufA[i * BP + pl + 64 * ip];
                u64 ed = pk2(e, e);
#pragma unroll
                for (int j = 0; j < 5; j++) fma2p(acc[ip][j], ed, wv[j]);
            }
        }
#pragma unroll
        for (int ip = 0; ip < 4; ip++) {
            int n = n0 + pl + 64 * ip;
            if (n < NPTS) {
#pragma unroll
                for (int j = 0; j < 5; j++) {
                    float a0, a1; upk2(acc[ip][j], a0, a1);
                    g_filt1[(s * C1_ + ob + 2*j)     * NPTS + n] = a0;
                    g_filt1[(s * C1_ + ob + 2*j + 1) * NPTS + n] = a1;
                }
            }
        }
    }
}

// ---------------- K2: g_z1[sc][b] += filt1 . data over 320-wide n-range -----------
// R7 tile (128sc x 64b, 256 thr, 4 sc-pairs x 4 b per thread) + DOUBLE BUFFERING:
// prefetch chunk ch+1 into regs before computing chunk ch; STS after compute;
// one bar per chunk. Division-free (r,k) walk: k += 16 mod 20, r += 12/13.
__device__ __forceinline__ void k2_load(const float* fp, const float* dp, int k0,
                                        float* fregs, float* dregs)
{
    int k = k0;
#pragma unroll
    for (int q = 0; q < 10; q++) {
        fregs[q] = __ldg(fp);
        bool w = (k >= 4);
        fp += w ? (13 * NPTS - 4) : (12 * NPTS + 16);
        k   = w ? (k - 4) : (k + 16);
    }
    k = k0;
#pragma unroll
    for (int q = 0; q < 5; q++) {
        dregs[q] = __ldg(dp);
        bool w = (k >= 4);
        dp += w ? (13 * NPTS - 4) : (12 * NPTS + 16);
        k   = w ? (k - 4) : (k + 16);
    }
}

__device__ __forceinline__ void k2_store(float* ft, u64* dt, int k0, int r0,
                                         const float* fregs, const float* dregs)
{
    int si = k0 * 130 + r0, k = k0;
#pragma unroll
    for (int q = 0; q < 10; q++) {
        ft[si] = fregs[q];
        bool w = (k >= 4);
        si += w ? (-4 * 130 + 13) : (16 * 130 + 12);
        k   = w ? (k - 4) : (k + 16);
    }
    si = k0 * 65 + r0; k = k0;
#pragma unroll
    for (int q = 0; q < 5; q++) {
        dt[si] = pk2(dregs[q], dregs[q]);
        bool w = (k >= 4);
        si += w ? (-4 * 65 + 13) : (16 * 65 + 12);
        k   = w ? (k - 4) : (k + 16);
    }
}

__global__ __launch_bounds__(256) void k2_z1(const float* __restrict__ data)
{
    __shared__ __align__(16) float ftb[2][KCH2 * 130];  // [buf][k][sc]  10.4 KB each
    __shared__ __align__(16) u64  dtb[2][KCH2 * 65];    // [buf][k][b] dup'd, 10.4 KB each

    int sc0   = blockIdx.x * 128;
    int split = blockIdx.y;
    int tid   = threadIdx.x;
    int bq    = tid & 15;     // b = bq + 16*jb
    int sq    = tid >> 4;     // sc-pair = sq + 16*ip  ->  sc = 2*pair

    int fr = tid / 20, fk = tid - fr * 20;   // this thread's load slot 0 (r, k)
    const float* fbase = &g_filt1[(sc0 + fr) * NPTS + split * 320 + fk];
    const float* dbase = &data[fr * NPTS + split * 320 + fk];

    float fregs[10], dregs[5];

    // prologue: chunk 0 -> buf 0
    k2_load(fbase, dbase, fk, fregs, dregs);
    fbase += KCH2; dbase += KCH2;
    k2_store(ftb[0], dtb[0], fk, fr, fregs, dregs);
    __syncthreads();

    u64 acc[4][4];
#pragma unroll
    for (int ip = 0; ip < 4; ip++)
#pragma unroll
        for (int jb = 0; jb < 4; jb++) acc[ip][jb] = 0ull;

    for (int ch = 0; ch < NCH2; ch++) {
        if (ch + 1 < NCH2) {
            k2_load(fbase, dbase, fk, fregs, dregs);   // prefetch next chunk
            fbase += KCH2; dbase += KCH2;
        }
        const float* ft = ftb[ch & 1];
        const u64*  dt = dtb[ch & 1];
#pragma unroll 4
        for (int k = 0; k < KCH2; k++) {
            u64 fd[4];
#pragma unroll
            for (int ip = 0; ip < 4; ip++)
                fd[ip] = *(const u64*)&ft[k * 130 + 2 * (sq + 16 * ip)];
            u64 dd[4];
#pragma unroll
            for (int jb = 0; jb < 4; jb++)
                dd[jb] = dt[k * 65 + bq + 16 * jb];
#pragma unroll
            for (int ip = 0; ip < 4; ip++)
#pragma unroll
                for (int jb = 0; jb < 4; jb++)
                    fma2p(acc[ip][jb], fd[ip], dd[jb]);
        }
        if (ch + 1 < NCH2)
            k2_store(ftb[(ch + 1) & 1], dtb[(ch + 1) & 1], fk, fr, fregs, dregs);
        __syncthreads();
    }

#pragma unroll
    for (int ip = 0; ip < 4; ip++) {
        int sc = sc0 + 2 * (sq + 16 * ip);
#pragma unroll
        for (int jb = 0; jb < 4; jb++) {
            int b = bq + 16 * jb;
            float a0, a1; upk2(acc[ip][jb], a0, a1);
            atomicAdd(&g_z1[sc * B_ + b],       a0);
            atomicAdd(&g_z1[(sc + 1) * B_ + b], a1);
        }
    }
}

// ---------------- K3a: h2[s,:] = silu(embed(v0[s]) @ s_w1 + s_b1) -----------------
__global__ __launch_bounds__(128) void k3a_h2(const float* __restrict__ v0,
                                              const float* __restrict__ s_w1,
                                              const float* __restrict__ s_b1)
{
    __shared__ float e[80];
    int s = blockIdx.x, tid = threadIdx.x;
    if (tid < 80) {
        int d = tid / 10, kk = tid % 10;
        float v = v0[s * 8 + d];
        float f = (float)(1 << (kk % 5));
        e[tid] = (kk < 5) ? __sinf(v * f) : __cosf(v * f);
    }
    __syncthreads();
    float a = s_b1[tid];
#pragma unroll 8
    for (int k = 0; k < 80; k++) a += e[k] * s_w1[k * W_ + tid];
    g_h2[s * W_ + tid] = silu_f(a);
}

// ---------------- KG: g_G[k,cb] += sum over 32 s of h2e[s,k] * silu(z1/N)[s,cb] ---
__global__ __launch_bounds__(256) void kG_contract()
{
    __shared__ float h2s[32 * 129];   // [sl][k], k==128 -> 1 (bias column)
    __shared__ float z1s[32 * 81];    // [sl][cbl]
    int cb0 = blockIdx.x * 80;
    int s0  = blockIdx.y * 32;
    int tid = threadIdx.x;

    for (int i = tid; i < 32 * 32; i += 256) {
        int r = i >> 5, k4 = i & 31;
        float4 v = *(const float4*)&g_h2[(s0 + r) * W_ + 4 * k4];
        h2s[r * 129 + 4 * k4 + 0] = v.x; h2s[r * 129 + 4 * k4 + 1] = v.y;
        h2s[r * 129 + 4 * k4 + 2] = v.z; h2s[r * 129 + 4 * k4 + 3] = v.w;
    }
    if (tid < 32) h2s[tid * 129 + 128] = 1.0f;

    for (int i = tid; i < 32 * 20; i += 256) {
        int r = i / 20, c4 = i - r * 20;
        float4 a = *(const float4*)&g_z1[(s0 + r) * 1280 + cb0 + 4 * c4];
        float* zr = &z1s[r * 81 + 4 * c4];
        zr[0] = silu_f(a.x * (1.0f / (float)NPTS));
        zr[1] = silu_f(a.y * (1.0f / (float)NPTS));
        zr[2] = silu_f(a.z * (1.0f / (float)NPTS));
        zr[3] = silu_f(a.w * (1.0f / (float)NPTS));
    }
    __syncthreads();

    int kq  = tid & 15;   // k = kq + 16*j (j<8), plus k=128 when kq==0
    int cbq = tid >> 4;   // cb = cbq + 16*i (i<5)

    float acc[9][5];
#pragma unroll
    for (int j = 0; j < 9; j++)
#pragma unroll
        for (int i = 0; i < 5; i++) acc[j][i] = 0.0f;

    for (int sl = 0; sl < 32; sl++) {
        float h[9];
#pragma unroll
        for (int j = 0; j < 8; j++) h[j] = h2s[sl * 129 + kq + 16 * j];
        h[8] = h2s[sl * 129 + 128];
        float z[5];
#pragma unroll
        for (int i = 0; i < 5; i++) z[i] = z1s[sl * 81 + cbq + 16 * i];
#pragma unroll
        for (int j = 0; j < 9; j++)
#pragma unroll
            for (int i = 0; i < 5; i++) acc[j][i] += h[j] * z[i];
    }

#pragma unroll
    for (int j = 0; j < 9; j++) {
        int k = kq + 16 * j;
        if (j < 8 || kq == 0) {
#pragma unroll
            for (int i = 0; i < 5; i++)
                atomicAdd(&g_G[k * 1280 + cb0 + cbq + 16 * i], acc[j][i]);
        }
    }
}

// ---------------- KZ: g_z2[b][w] += sum over 30 kc of G[k,cb] * W2ext -------------
__global__ __launch_bounds__(256) void kZ_out(const float* __restrict__ s_w2,
                                              const float* __restrict__ s_b2)
{
    __shared__ float Gt[30 * 64];    // [kcl][b]
    __shared__ float Wt[30 * 128];   // [kcl][w]
    int kc0 = blockIdx.x * 30;
    int tid = threadIdx.x;

    for (int i = tid; i < 30 * 32; i += 256) {
        int kcl = i >> 5, w4 = i & 31;
        int kc = kc0 + kcl, k = kc / 20, c = kc - k * 20;
        float4 v = (k < 128) ? *(const float4*)&s_w2[k * 2560 + c * 128 + 4 * w4]
                             : *(const float4*)&s_b2[c * 128 + 4 * w4];
        *(float4*)&Wt[kcl * 128 + 4 * w4] = v;
    }
    for (int i = tid; i < 30 * 16; i += 256) {
        int kcl = i >> 4, b4 = i & 15;
        int kc = kc0 + kcl, k = kc / 20, c = kc - k * 20;
        float4 a = *(const float4*)&g_G[k * 1280 + c * 64 + 4 * b4];
        *(float4*)&Gt[kcl * 64 + 4 * b4] = a;
    }
    __syncthreads();

    int wq = tid & 15;   // w = wq + 16*m
    int bq = tid >> 4;   // b = bq + 16*i
    float acc[4][8];
#pragma unroll
    for (int i = 0; i < 4; i++)
#pragma unroll
        for (int m = 0; m < 8; m++) acc[i][m] = 0.0f;

    for (int kcl = 0; kcl < 30; kcl++) {
        float g[4];
#pragma unroll
        for (int i = 0; i < 4; i++) g[i] = Gt[kcl * 64 + bq + 16 * i];
#pragma unroll
        for (int m = 0; m < 8; m++) {
            float w = Wt[kcl * 128 + wq + 16 * m];
#pragma unroll
            for (int i = 0; i < 4; i++) acc[i][m] += g[i] * w;
        }
    }
#pragma unroll
    for (int i = 0; i < 4; i++)
#pragma unroll
        for (int m = 0; m < 8; m++)
            atomicAdd(&g_z2[(bq + 16 * i) * W_ + wq + 16 * m], acc[i][m]);
}

// ---------------- K5: residual MLP + pool -----------------------------------------
__global__ __launch_bounds__(128) void k5_head(const float* __restrict__ fc1_w,
                                               const float* __restrict__ fc1_b,
                                               const float* __restrict__ fc2_w,
                                               const float* __restrict__ fc2_b,
                                               const float* __restrict__ pool_w,
                                               const float* __restrict__ pool_b,
                                               float* __restrict__ out)
{
    __shared__ float zs[128], r1[128], r2[128];
    int b = blockIdx.x, w = threadIdx.x;

    float a = g_z2[b * W_ + w] * (1.0f / (float)S_);
    zs[w] = a;
    __syncthreads();

    float u = fc1_b[w];
#pragma unroll 8
    for (int k = 0; k < 128; k++) u += zs[k] * fc1_w[k * W_ + w];
    r1[w] = silu_f(u) + zs[w];
    __syncthreads();

    u = fc2_b[w];
#pragma unroll 8
    for (int k = 0; k < 128; k++) u += r1[k] * fc2_w[k * W_ + w];
    r2[w] = silu_f(u) + r1[w];
    __syncthreads();

    if (w < 10) {
        float o = pool_b[w];
        for (int k = 0; k < 128; k++) o += r2[k] * pool_w[k * 10 + w];
        out[b * 10 + w] = o;
    }
}

// ---------------- host launcher ---------------------------------------------------
extern "C" void kernel_launch(void* const* d_in, const int* in_sizes, int n_in,
                              void* d_out, int out_size)
{
    const float* data   = (const float*)d_in[0];
    const float* v0     = (const float*)d_in[1];
    const float* v_last = (const float*)d_in[2];
    const float* fl_w1  = (const float*)d_in[3];
    const float* fl_b1  = (const float*)d_in[4];
    const float* fl_w2  = (const float*)d_in[5];
    const float* fl_b2  = (const float*)d_in[6];
    const float* fl_w3  = (const float*)d_in[7];
    const float* fl_b3  = (const float*)d_in[8];
    const float* s_w1   = (const float*)d_in[9];
    const float* s_b1   = (const float*)d_in[10];
    const float* s_w2   = (const float*)d_in[11];
    const float* s_b2   = (const float*)d_in[12];
    const float* fc1_w  = (const float*)d_in[13];
    const float* fc1_b  = (const float*)d_in[14];
    const float* fc2_w  = (const float*)d_in[15];
    const float* fc2_b  = (const float*)d_in[16];
    const float* pool_w = (const float*)d_in[17];
    const float* pool_b = (const float*)d_in[18];

    kzero<<<640, 256>>>();
    k3a_h2<<<S_, 128>>>(v0, s_w1, s_b1);
    k1_filt1<<<dim3(7, S_), 128>>>(v_last, fl_w1, fl_b1, fl_w2, fl_b2, fl_w3, fl_b3);
    k2_z1<<<dim3(80, KSPLIT), 256>>>(data);
    kG_contract<<<dim3(16, GSPLIT), 256>>>();
    kZ_out<<<ZSPLIT, 256>>>(s_w2, s_b2);
    k5_head<<<B_, 128>>>(fc1_w, fc1_b, fc2_w, fc2_b, pool_w, pool_b, (float*)d_out);
}

// round 10
// speedup vs baseline: 1.2449x; 1.0048x over previous
#include <cuda_runtime.h>
#include <math.h>

#define B_     64
#define NSIDE  40
#define NPTS   1600
#define S_     512
#define C1_    20
#define W_     128
#define SCN    10240                 // S_*C1_
#define KSPLIT 5                     // k2 n-dim split (320 each)
#define GSPLIT 16                    // kG s-splits (32 s each)
#define ZSPLIT 86                    // kZ kc-splits (30 each)
#define KCH2   20                    // k2 k-chunk
#define NCH2   16                    // chunks per 320-split

typedef unsigned long long u64;

// ---------------- scratch (device globals; no runtime allocation) ----------------
__device__ __align__(16) float g_filt1[S_ * C1_ * NPTS];   // [sc][n]
__device__ __align__(16) float g_z1  [SCN * B_];           // atomic accum [sc][b]
__device__ __align__(16) float g_h2  [S_ * W_];            // [s][128]
__device__ __align__(16) float g_G   [129 * 1280];         // atomic accum [k][c*64+b]
__device__ __align__(16) float g_z2  [B_ * W_];            // atomic accum [b][w]

// ---------------- f32x2 helpers (Blackwell packed fp32 FMA) -----------------------
__device__ __forceinline__ u64 pk2(float lo, float hi) {
    u64 r; asm("mov.b64 %0, {%1, %2};" : "=l"(r) : "f"(lo), "f"(hi)); return r;
}
__device__ __forceinline__ void upk2(u64 v, float& lo, float& hi) {
    asm("mov.b64 {%0, %1}, %2;" : "=f"(lo), "=f"(hi) : "l"(v));
}
__device__ __forceinline__ void fma2p(u64& d, u64 a, u64 b) {
    asm("fma.rn.f32x2 %0, %1, %2, %0;" : "+l"(d) : "l"(a), "l"(b));
}

__device__ __forceinline__ float silu_f(float x) { return x / (1.0f + __expf(-x)); }
__device__ __forceinline__ float silu_t(float x) {
    float t; asm("tanh.approx.f32 %0, %1;" : "=f"(t) : "f"(0.5f * x));
    return 0.5f * x * (1.0f + t);
}

// ---------------- K0: zero the atomic accumulators (per replay) -------------------
__global__ __launch_bounds__(256) void kzero()
{
    int i = blockIdx.x * 256 + threadIdx.x;
    float4 z = make_float4(0.f, 0.f, 0.f, 0.f);
    ((float4*)g_z1)[i] = z;                        // 163840 float4
    if (i < 129 * 1280 / 4) ((float4*)g_G)[i] = z;
    if (i < B_ * W_ / 4)    ((float4*)g_z2)[i] = z;
}

// ---------------- K1: filt1[sc][n] = MLP(embed(projective coords)) ----------------
#define BP 264   // buf row stride [feat][point]

__device__ __forceinline__ void k1_layer(const float* in, float* out,
                                         const float* w, const float* bias,
                                         int og, int pl)
{
    int ob = og * 10;
    u64 acc[4][5];
#pragma unroll
    for (int ip = 0; ip < 4; ip++)
#pragma unroll
        for (int j = 0; j < 5; j++) acc[ip][j] = pk2(bias[ob + 2*j], bias[ob + 2*j + 1]);
#pragma unroll 4
    for (int i = 0; i < 20; i++) {
        u64 wv[5];
#pragma unroll
        for (int j = 0; j < 5; j++)
            wv[j] = *(const u64*)&w[i * 20 + ob + 2 * j];
#pragma unroll
        for (int ip = 0; ip < 4; ip++) {
            float e = in[i * BP + pl + 64 * ip];
            u64 ed = pk2(e, e);
#pragma unroll
            for (int j = 0; j < 5; j++) fma2p(acc[ip][j], ed, wv[j]);
        }
    }
#pragma unroll
    for (int ip = 0; ip < 4; ip++)
#pragma unroll
        for (int j = 0; j < 5; j++) {
            float a0, a1; upk2(acc[ip][j], a0, a1);
            out[(ob + 2*j)     * BP + pl + 64 * ip] = silu_t(a0);
            out[(ob + 2*j + 1) * BP + pl + 64 * ip] = silu_t(a1);
        }
}

__global__ __launch_bounds__(128) void k1_filt1(
    const float* __restrict__ v_last,
    const float* __restrict__ fw1, const float* __restrict__ fb1,
    const float* __restrict__ fw2, const float* __restrict__ fb2,
    const float* __restrict__ fw3, const float* __restrict__ fb3)
{
    __shared__ __align__(16) float sw1[400], sw2[400], sw3[400];
    __shared__ float sb1[20], sb2[20], sb3[20];
    __shared__ __align__(16) float bufA[20 * BP], bufB[20 * BP];

    int s   = blockIdx.y;
    int n0  = blockIdx.x * 256;
    int tid = threadIdx.x;

    for (int i = tid; i < 400; i += 128) { sw1[i] = fw1[i]; sw2[i] = fw2[i]; sw3[i] = fw3[i]; }
    if (tid < 20) { sb1[tid] = fb1[tid]; sb2[tid] = fb2[tid]; sb3[tid] = fb3[tid]; }

    float v[8];
#pragma unroll
    for (int i = 0; i < 8; i++) v[i] = 0.1f * __ldg(&v_last[s * 8 + i]);

#pragma unroll
    for (int q = 0; q < 2; q++) {
        int p = tid + q * 128;
        int n = n0 + p;
        int ic = n / NSIDE, jc = n - ic * NSIDE;
        float x = -1.0f + (2.0f / 39.0f) * (float)ic;
        float y = -1.0f + (2.0f / 39.0f) * (float)jc;
        float y0 = (1.0f + v[0]) * x + v[1] * y + v[2];
        float y1 = v[3] * x + (1.0f + v[4]) * y + v[5];
        float y2 = v[6] * x + v[7] * y + 1.0f;
        float inv = __frcp_rn(y2);
        float t0 = y0 * inv, t1 = y1 * inv;

        float sa, ca; __sincosf(t0, &sa, &ca);
        bufA[0 * BP + p] = sa; bufA[5 * BP + p] = ca;
#pragma unroll
        for (int k = 1; k < 5; k++) {
            float s2 = 2.0f * sa * ca;
            float c2 = 2.0f * ca * ca - 1.0f;
            bufA[k * BP + p] = s2; bufA[(5 + k) * BP + p] = c2;
            sa = s2; ca = c2;
        }
        __sincosf(t1, &sa, &ca);
        bufA[10 * BP + p] = sa; bufA[15 * BP + p] = ca;
#pragma unroll
        for (int k = 1; k < 5; k++) {
            float s2 = 2.0f * sa * ca;
            float c2 = 2.0f * ca * ca - 1.0f;
            bufA[(10 + k) * BP + p] = s2; bufA[(15 + k) * BP + p] = c2;
            sa = s2; ca = c2;
        }
    }
    __syncthreads();

    int og = tid >> 6;
    int pl = tid & 63;

    k1_layer(bufA, bufB, sw1, sb1, og, pl);
    __syncthreads();
    k1_layer(bufB, bufA, sw2, sb2, og, pl);
    __syncthreads();

    {
        int ob = og * 10;
        u64 acc[4][5];
#pragma unroll
        for (int ip = 0; ip < 4; ip++)
#pragma unroll
            for (int j = 0; j < 5; j++) acc[ip][j] = pk2(sb3[ob + 2*j], sb3[ob + 2*j + 1]);
#pragma unroll 4
        for (int i = 0; i < 20; i++) {
            u64 wv[5];
#pragma unroll
            for (int j = 0; j < 5; j++) wv[j] = *(const u64*)&sw3[i * 20 + ob + 2 * j];
#pragma unroll
            for (int ip = 0; ip < 4; ip++) {
                float e = bufA[i * BP + pl + 64 * ip];
                u64 ed = pk2(e, e);
#pragma unroll
                for (int j = 0; j < 5; j++) fma2p(acc[ip][j], ed, wv[j]);
            }
        }
#pragma unroll
        for (int ip = 0; ip < 4; ip++) {
            int n = n0 + pl + 64 * ip;
            if (n < NPTS) {
#pragma unroll
                for (int j = 0; j < 5; j++) {
                    float a0, a1; upk2(acc[ip][j], a0, a1);
                    g_filt1[(s * C1_ + ob + 2*j)     * NPTS + n] = a0;
                    g_filt1[(s * C1_ + ob + 2*j + 1) * NPTS + n] = a1;
                }
            }
        }
    }
}

// ---------------- K2: g_z1[sc][b] += filt1 . data over 320-wide n-range -----------
// R9 double-buffered structure; pairing FLIPPED: acc pairs along b (natural data
// pairs from a plain-float tile), filter dup'd as u64 consumed via LDS.128
// broadcast. Per warp-k: 2 LDS.128 (fd) + 4 LDS.64 (dd) = 6 wf vs 8 FMA-cyc.
__device__ __forceinline__ void k2_load(const float* fp, const float* dp, int k0,
                                        float* fregs, float* dregs)
{
    int k = k0;
#pragma unroll
    for (int q = 0; q < 10; q++) {
        fregs[q] = __ldg(fp);
        bool w = (k >= 4);
        fp += w ? (13 * NPTS - 4) : (12 * NPTS + 16);
        k   = w ? (k - 4) : (k + 16);
    }
    k = k0;
#pragma unroll
    for (int q = 0; q < 5; q++) {
        dregs[q] = __ldg(dp);
        bool w = (k >= 4);
        dp += w ? (13 * NPTS - 4) : (12 * NPTS + 16);
        k   = w ? (k - 4) : (k + 16);
    }
}

__device__ __forceinline__ void k2_store(u64* ftd, float* dt, int k0, int r0,
                                         const float* fregs, const float* dregs)
{
    int si = k0 * 130 + r0, k = k0;
#pragma unroll
    for (int q = 0; q < 10; q++) {
        ftd[si] = pk2(fregs[q], fregs[q]);         // dup-pack filter
        bool w = (k >= 4);
        si += w ? (-4 * 130 + 13) : (16 * 130 + 12);
        k   = w ? (k - 4) : (k + 16);
    }
    si = k0 * 66 + r0; k = k0;
#pragma unroll
    for (int q = 0; q < 5; q++) {
        dt[si] = dregs[q];                          // natural data
        bool w = (k >= 4);
        si += w ? (-4 * 66 + 13) : (16 * 66 + 12);
        k   = w ? (k - 4) : (k + 16);
    }
}

__global__ __launch_bounds__(256, 3) void k2_z1(const float* __restrict__ data)
{
    __shared__ __align__(16) u64  ftb[2][KCH2 * 130];   // [buf][k][sc] dup'd, 20.8 KB each
    __shared__ __align__(16) float dtb[2][KCH2 * 66];   // [buf][k][b] natural, 5.3 KB each

    int sc0   = blockIdx.x * 128;
    int split = blockIdx.y;
    int tid   = threadIdx.x;
    int bq    = tid & 7;      // b-pair: b = 2*bq + 16*jb + {0,1}
    int sr    = tid >> 3;     // sc group: sc = 4*sr + p

    int fr = tid / 20, fk = tid - fr * 20;   // this thread's load slot 0 (r, k)
    const float* fbase = &g_filt1[(sc0 + fr) * NPTS + split * 320 + fk];
    const float* dbase = &data[fr * NPTS + split * 320 + fk];

    float fregs[10], dregs[5];

    // prologue: chunk 0 -> buf 0
    k2_load(fbase, dbase, fk, fregs, dregs);
    fbase += KCH2; dbase += KCH2;
    k2_store(ftb[0], dtb[0], fk, fr, fregs, dregs);
    __syncthreads();

    u64 acc[4][4];            // [sc p][b-pair jb]
#pragma unroll
    for (int p = 0; p < 4; p++)
#pragma unroll
        for (int jb = 0; jb < 4; jb++) acc[p][jb] = 0ull;

    for (int ch = 0; ch < NCH2; ch++) {
        if (ch + 1 < NCH2) {
            k2_load(fbase, dbase, fk, fregs, dregs);   // prefetch next chunk
            fbase += KCH2; dbase += KCH2;
        }
        const u64*  ft = ftb[ch & 1];
        const float* dt = dtb[ch & 1];
#pragma unroll 4
        for (int k = 0; k < KCH2; k++) {
            ulonglong2 fA = *(const ulonglong2*)&ft[k * 130 + 4 * sr];
            ulonglong2 fB = *(const ulonglong2*)&ft[k * 130 + 4 * sr + 2];
            u64 fd[4] = { fA.x, fA.y, fB.x, fB.y };
            u64 dd[4];
#pragma unroll
            for (int jb = 0; jb < 4; jb++)
                dd[jb] = *(const u64*)&dt[k * 66 + 2 * bq + 16 * jb];
#pragma unroll
            for (int p = 0; p < 4; p++)
#pragma unroll
                for (int jb = 0; jb < 4; jb++)
                    fma2p(acc[p][jb], fd[p], dd[jb]);
        }
        if (ch + 1 < NCH2)
            k2_store(ftb[(ch + 1) & 1], dtb[(ch + 1) & 1], fk, fr, fregs, dregs);
        __syncthreads();
    }

#pragma unroll
    for (int p = 0; p < 4; p++) {
        int sc = sc0 + 4 * sr + p;
#pragma unroll
        for (int jb = 0; jb < 4; jb++) {
            int b = 2 * bq + 16 * jb;
            float a0, a1; upk2(acc[p][jb], a0, a1);
            atomicAdd(&g_z1[sc * B_ + b],     a0);
            atomicAdd(&g_z1[sc * B_ + b + 1], a1);
        }
    }
}

// ---------------- K3a: h2[s,:] = silu(embed(v0[s]) @ s_w1 + s_b1) -----------------
__global__ __launch_bounds__(128) void k3a_h2(const float* __restrict__ v0,
                                              const float* __restrict__ s_w1,
                                              const float* __restrict__ s_b1)
{
    __shared__ float e[80];
    int s = blockIdx.x, tid = threadIdx.x;
    if (tid < 80) {
        int d = tid / 10, kk = tid % 10;
        float v = v0[s * 8 + d];
        float f = (float)(1 << (kk % 5));
        e[tid] = (kk < 5) ? __sinf(v * f) : __cosf(v * f);
    }
    __syncthreads();
    float a = s_b1[tid];
#pragma unroll 8
    for (int k = 0; k < 80; k++) a += e[k] * s_w1[k * W_ + tid];
    g_h2[s * W_ + tid] = silu_f(a);
}

// ---------------- KG: g_G[k,cb] += sum over 32 s of h2e[s,k] * silu(z1/N)[s,cb] ---
__global__ __launch_bounds__(256) void kG_contract()
{
    __shared__ float h2s[32 * 129];   // [sl][k], k==128 -> 1 (bias column)
    __shared__ float z1s[32 * 81];    // [sl][cbl]
    int cb0 = blockIdx.x * 80;
    int s0  = blockIdx.y * 32;
    int tid = threadIdx.x;

    for (int i = tid; i < 32 * 32; i += 256) {
        int r = i >> 5, k4 = i & 31;
        float4 v = *(const float4*)&g_h2[(s0 + r) * W_ + 4 * k4];
        h2s[r * 129 + 4 * k4 + 0] = v.x; h2s[r * 129 + 4 * k4 + 1] = v.y;
        h2s[r * 129 + 4 * k4 + 2] = v.z; h2s[r * 129 + 4 * k4 + 3] = v.w;
    }
    if (tid < 32) h2s[tid * 129 + 128] = 1.0f;

    for (int i = tid; i < 32 * 20; i += 256) {
        int r = i / 20, c4 = i - r * 20;
        float4 a = *(const float4*)&g_z1[(s0 + r) * 1280 + cb0 + 4 * c4];
        float* zr = &z1s[r * 81 + 4 * c4];
        zr[0] = silu_f(a.x * (1.0f / (float)NPTS));
        zr[1] = silu_f(a.y * (1.0f / (float)NPTS));
        zr[2] = silu_f(a.z * (1.0f / (float)NPTS));
        zr[3] = silu_f(a.w * (1.0f / (float)NPTS));
    }
    __syncthreads();

    int kq  = tid & 15;   // k = kq + 16*j (j<8), plus k=128 when kq==0
    int cbq = tid >> 4;   // cb = cbq + 16*i (i<5)

    float acc[9][5];
#pragma unroll
    for (int j = 0; j < 9; j++)
#pragma unroll
        for (int i = 0; i < 5; i++) acc[j][i] = 0.0f;

    for (int sl = 0; sl < 32; sl++) {
        float h[9];
#pragma unroll
        for (int j = 0; j < 8; j++) h[j] = h2s[sl * 129 + kq + 16 * j];
        h[8] = h2s[sl * 129 + 128];
        float z[5];
#pragma unroll
        for (int i = 0; i < 5; i++) z[i] = z1s[sl * 81 + cbq + 16 * i];
#pragma unroll
        for (int j = 0; j < 9; j++)
#pragma unroll
            for (int i = 0; i < 5; i++) acc[j][i] += h[j] * z[i];
    }

#pragma unroll
    for (int j = 0; j < 9; j++) {
        int k = kq + 16 * j;
        if (j < 8 || kq == 0) {
#pragma unroll
            for (int i = 0; i < 5; i++)
                atomicAdd(&g_G[k * 1280 + cb0 + cbq + 16 * i], acc[j][i]);
        }
    }
}

// ---------------- KZ: g_z2[b][w] += sum over 30 kc of G[k,cb] * W2ext -------------
__global__ __launch_bounds__(256) void kZ_out(const float* __restrict__ s_w2,
                                              const float* __restrict__ s_b2)
{
    __shared__ float Gt[30 * 64];    // [kcl][b]
    __shared__ float Wt[30 * 128];   // [kcl][w]
    int kc0 = blockIdx.x * 30;
    int tid = threadIdx.x;

    for (int i = tid; i < 30 * 32; i += 256) {
        int kcl = i >> 5, w4 = i & 31;
        int kc = kc0 + kcl, k = kc / 20, c = kc - k * 20;
        float4 v = (k < 128) ? *(const float4*)&s_w2[k * 2560 + c * 128 + 4 * w4]
                             : *(const float4*)&s_b2[c * 128 + 4 * w4];
        *(float4*)&Wt[kcl * 128 + 4 * w4] = v;
    }
    for (int i = tid; i < 30 * 16; i += 256) {
        int kcl = i >> 4, b4 = i & 15;
        int kc = kc0 + kcl, k = kc / 20, c = kc - k * 20;
        float4 a = *(const float4*)&g_G[k * 1280 + c * 64 + 4 * b4];
        *(float4*)&Gt[kcl * 64 + 4 * b4] = a;
    }
    __syncthreads();

    int wq = tid & 15;   // w = wq + 16*m
    int bq = tid >> 4;   // b = bq + 16*i
    float acc[4][8];
#pragma unroll
    for (int i = 0; i < 4; i++)
#pragma unroll
        for (int m = 0; m < 8; m++) acc[i][m] = 0.0f;

    for (int kcl = 0; kcl < 30; kcl++) {
        float g[4];
#pragma unroll
        for (int i = 0; i < 4; i++) g[i] = Gt[kcl * 64 + bq + 16 * i];
#pragma unroll
        for (int m = 0; m < 8; m++) {
            float w = Wt[kcl * 128 + wq + 16 * m];
#pragma unroll
            for (int i = 0; i < 4; i++) acc[i][m] += g[i] * w;
        }
    }
#pragma unroll
    for (int i = 0; i < 4; i++)
#pragma unroll
        for (int m = 0; m < 8; m++)
            atomicAdd(&g_z2[(bq + 16 * i) * W_ + wq + 16 * m], acc[i][m]);
}

// ---------------- K5: residual MLP + pool -----------------------------------------
__global__ __launch_bounds__(128) void k5_head(const float* __restrict__ fc1_w,
                                               const float* __restrict__ fc1_b,
                                               const float* __restrict__ fc2_w,
                                               const float* __restrict__ fc2_b,
                                               const float* __restrict__ pool_w,
                                               const float* __restrict__ pool_b,
                                               float* __restrict__ out)
{
    __shared__ float zs[128], r1[128], r2[128];
    int b = blockIdx.x, w = threadIdx.x;

    float a = g_z2[b * W_ + w] * (1.0f / (float)S_);
    zs[w] = a;
    __syncthreads();

    float u = fc1_b[w];
#pragma unroll 8
    for (int k = 0; k < 128; k++) u += zs[k] * fc1_w[k * W_ + w];
    r1[w] = silu_f(u) + zs[w];
    __syncthreads();

    u = fc2_b[w];
#pragma unroll 8
    for (int k = 0; k < 128; k++) u += r1[k] * fc2_w[k * W_ + w];
    r2[w] = silu_f(u) + r1[w];
    __syncthreads();

    if (w < 10) {
        float o = pool_b[w];
        for (int k = 0; k < 128; k++) o += r2[k] * pool_w[k * 10 + w];
        out[b * 10 + w] = o;
    }
}

// ---------------- host launcher ---------------------------------------------------
extern "C" void kernel_launch(void* const* d_in, const int* in_sizes, int n_in,
                              void* d_out, int out_size)
{
    const float* data   = (const float*)d_in[0];
    const float* v0     = (const float*)d_in[1];
    const float* v_last = (const float*)d_in[2];
    const float* fl_w1  = (const float*)d_in[3];
    const float* fl_b1  = (const float*)d_in[4];
    const float* fl_w2  = (const float*)d_in[5];
    const float* fl_b2  = (const float*)d_in[6];
    const float* fl_w3  = (const float*)d_in[7];
    const float* fl_b3  = (const float*)d_in[8];
    const float* s_w1   = (const float*)d_in[9];
    const float* s_b1   = (const float*)d_in[10];
    const float* s_w2   = (const float*)d_in[11];
    const float* s_b2   = (const float*)d_in[12];
    const float* fc1_w  = (const float*)d_in[13];
    const float* fc1_b  = (const float*)d_in[14];
    const float* fc2_w  = (const float*)d_in[15];
    const float* fc2_b  = (const float*)d_in[16];
    const float* pool_w = (const float*)d_in[17];
    const float* pool_b = (const float*)d_in[18];

    kzero<<<640, 256>>>();
    k3a_h2<<<S_, 128>>>(v0, s_w1, s_b1);
    k1_filt1<<<dim3(7, S_), 128>>>(v_last, fl_w1, fl_b1, fl_w2, fl_b2, fl_w3, fl_b3);
    k2_z1<<<dim3(80, KSPLIT), 256>>>(data);
    kG_contract<<<dim3(16, GSPLIT), 256>>>();
    kZ_out<<<ZSPLIT, 256>>>(s_w2, s_b2);
    k5_head<<<B_, 128>>>(fc1_w, fc1_b, fc2_w, fc2_b, pool_w, pool_b, (float*)d_out);
}